// round 5
// baseline (speedup 1.0000x reference)
#include <cuda_runtime.h>
#include <math.h>

#define NBLK1 2048
#define LOG2E 1.44269504088896f
typedef unsigned long long ULL;

__device__ __align__(16) float g_ypre[4194304];   // (b,h,w,c)
__device__ float g_part[NBLK1 * 8];
__device__ float g_stats[32];

// shared-memory float offsets (packed accesses all 8B-aligned)
#define OFF_WIN   0        // [32][128]
#define OFF_WX    4096     // [64][34]
#define OFF_WOUT  6272     // [64][32]
#define OFF_WDT   8320     // [2][64]
#define OFF_BDT2  8448     // [64]
#define OFF_DS2   8512     // [64]
// union: XF (GEMM1 input) aliases B/C/DTSR (written by GEMM2 after XF is dead)
#define OFF_XF    8576     // [64][33] = 2112
#define OFF_B     8576     // [64][16]
#define OFF_C     9600     // [64][16]
#define OFF_DTSR  10624    // [64][2]
#define OFF_XP    10752    // [64][66]  (aliased by YS)
#define OFF_YS    10752
#define OFF_GZ    14976    // [64][66]
#define OFF_GACC  19200    // [8][4][2]
#define SMEM_FLOATS 19264  // 77056 B -> 3 CTAs/SM

__device__ __forceinline__ float ex2f(float x) {
    float y; asm("ex2.approx.ftz.f32 %0, %1;" : "=f"(y) : "f"(x)); return y;
}
__device__ __forceinline__ ULL pack2(float lo, float hi) {
    ULL d; asm("mov.b64 %0, {%1, %2};" : "=l"(d) : "f"(lo), "f"(hi)); return d;
}
__device__ __forceinline__ ULL dup2(float v) { return pack2(v, v); }
__device__ __forceinline__ void unpack2(ULL v, float& lo, float& hi) {
    asm("mov.b64 {%0, %1}, %2;" : "=f"(lo), "=f"(hi) : "l"(v));
}
__device__ __forceinline__ ULL f2fma(ULL a, ULL b, ULL c) {
    ULL d; asm("fma.rn.f32x2 %0, %1, %2, %3;" : "=l"(d) : "l"(a), "l"(b), "l"(c)); return d;
}
__device__ __forceinline__ ULL f2mul(ULL a, ULL b) {
    ULL d; asm("mul.rn.f32x2 %0, %1, %2;" : "=l"(d) : "l"(a), "l"(b)); return d;
}
__device__ __forceinline__ float softplusf(float v) {
    float e = __expf(v);
    return (v < -3.0f) ? e * (1.0f - e * (0.5f - 0.33333334f * e)) : log1pf(e);
}
__device__ __forceinline__ float geluf(float v) {
    return 0.5f * v * (1.0f + erff(v * 0.70710678118f));
}

__global__ __launch_bounds__(256, 3) void k1_main(
    const float* __restrict__ x, const float* __restrict__ W_in,
    const float* __restrict__ W_x, const float* __restrict__ W_dt,
    const float* __restrict__ b_dt, const float* __restrict__ A_logs,
    const float* __restrict__ Ds, const float* __restrict__ W_out)
{
    extern __shared__ float S[];
    const int tid = threadIdx.x;
    const int bid = blockIdx.x;

    // ---------------- weights to smem ----------------
    for (int i = tid; i < 4096; i += 256) S[OFF_WIN + i] = W_in[i];
    for (int i = tid; i < 64 * 34; i += 256) S[OFF_WX + i] = W_x[i];
    for (int i = tid; i < 2048; i += 256) S[OFF_WOUT + i] = W_out[i];
    if (tid < 128) S[OFF_WDT + tid] = W_dt[tid];
    if (tid < 64) {
        S[OFF_BDT2 + tid] = 2.0f * b_dt[tid];
        S[OFF_DS2 + tid]  = 2.0f * Ds[tid];
    }
    int ok = 1;
    for (int i = tid; i < 1024; i += 256) {
        int n = i & 15;
        float ae = __expf(A_logs[i]);
        if (fabsf(ae - (float)(n + 1)) > 1e-3f * (float)(n + 1)) ok = 0;
    }

    // ---------------- x tile (8 consecutive w positions) ----------------
    {
        int m0 = bid * 8;
        int b = m0 >> 12;
        int h = (m0 >> 6) & 63;
        int w0 = m0 & 63;
        const float* xb = x + b * (256 * 4096) + h * 64 + w0;
        for (int i = tid; i < 2048; i += 256) {
            int c = i >> 3, p = i & 7;
            int t = c >> 5, g = c & 31;
            S[OFF_XF + (p * 8 + t) * 33 + g] = xb[c * 4096 + p];
        }
    }
    const int fast = __syncthreads_and(ok);

    // ---------------- GEMM1: [64x32]@[32x128] -> xp | gelu(z), packed ----------------
    {
        const int rp = tid >> 3, cg = tid & 7;
        const int row0 = 2 * rp, row1 = row0 + 1;
        ULL acc0[8], acc1[8];
        #pragma unroll
        for (int q = 0; q < 8; q++) { acc0[q] = 0ULL; acc1[q] = 0ULL; }
        const ULL* W4 = reinterpret_cast<const ULL*>(&S[OFF_WIN]);
        #pragma unroll 4
        for (int k = 0; k < 32; k++) {
            ULL a0p = dup2(S[OFF_XF + row0 * 33 + k]);
            ULL a1p = dup2(S[OFF_XF + row1 * 33 + k]);
            const ULL* wrow = W4 + k * 64 + cg * 8;
            #pragma unroll
            for (int q = 0; q < 8; q++) {
                ULL w = wrow[q];
                acc0[q] = f2fma(a0p, w, acc0[q]);
                acc1[q] = f2fma(a1p, w, acc1[q]);
            }
        }
        if (cg < 4) {
            ULL* X0 = reinterpret_cast<ULL*>(&S[OFF_XP + row0 * 66 + cg * 16]);
            ULL* X1 = reinterpret_cast<ULL*>(&S[OFF_XP + row1 * 66 + cg * 16]);
            #pragma unroll
            for (int q = 0; q < 8; q++) { X0[q] = acc0[q]; X1[q] = acc1[q]; }
        } else {
            int c0 = (cg - 4) * 16;
            #pragma unroll
            for (int q = 0; q < 8; q++) {
                float v0, v1, w0, w1;
                unpack2(acc0[q], v0, v1);
                unpack2(acc1[q], w0, w1);
                S[OFF_GZ + row0 * 66 + c0 + 2 * q]     = geluf(v0);
                S[OFF_GZ + row0 * 66 + c0 + 2 * q + 1] = geluf(v1);
                S[OFF_GZ + row1 * 66 + c0 + 2 * q]     = geluf(w0);
                S[OFF_GZ + row1 * 66 + c0 + 2 * q + 1] = geluf(w1);
            }
        }
    }
    __syncthreads();

    // ---------------- GEMM2: [64x64]@[64x34] -> dts(0,1)|B(2..17)|C(18..33) ----------------
    if (tid < 128) {
        const int rq = tid >> 3, cq = tid & 7;
        ULL accp[4][2];
        #pragma unroll
        for (int i = 0; i < 4; i++) { accp[i][0] = 0ULL; accp[i][1] = 0ULL; }
        #pragma unroll 4
        for (int k = 0; k < 64; k++) {
            const ULL* wp = reinterpret_cast<const ULL*>(&S[OFF_WX + k * 34 + 4 * cq]);
            ULL w0 = wp[0], w1 = wp[1];
            #pragma unroll
            for (int i = 0; i < 4; i++) {
                ULL ap = dup2(S[OFF_XP + (4 * rq + i) * 66 + k]);
                accp[i][0] = f2fma(ap, w0, accp[i][0]);
                accp[i][1] = f2fma(ap, w1, accp[i][1]);
            }
        }
        #pragma unroll
        for (int i = 0; i < 4; i++) {
            int r = 4 * rq + i;
            #pragma unroll
            for (int pp = 0; pp < 2; pp++) {
                int c0 = 4 * cq + 2 * pp;
                ULL v = accp[i][pp];
                if (c0 == 0)
                    reinterpret_cast<ULL*>(&S[OFF_DTSR])[r] = v;
                else if (c0 < 18)
                    *reinterpret_cast<ULL*>(&S[OFF_B + r * 16 + (c0 - 2)]) = v;
                else
                    *reinterpret_cast<ULL*>(&S[OFF_C + r * 16 + (c0 - 18)]) = v;
            }
        }
    } else if (tid < 192) {
        // cols 32,33 -> C[14],C[15]
        int r = tid - 128;
        ULL acc = 0ULL;
        #pragma unroll 8
        for (int k = 0; k < 64; k++) {
            ULL w = *reinterpret_cast<const ULL*>(&S[OFF_WX + k * 34 + 32]);
            acc = f2fma(dup2(S[OFF_XP + r * 66 + k]), w, acc);
        }
        *reinterpret_cast<ULL*>(&S[OFF_C + r * 16 + 14]) = acc;
    }
    __syncthreads();

    // ---------------- bidirectional selective scan (packed states) ----------------
    {
        const int p  = tid >> 5;
        const int d0 = tid & 31;
        float du0[8], du1[8];
        #pragma unroll
        for (int t = 0; t < 8; t++) {
            int r = p * 8 + t;
            float q0 = S[OFF_DTSR + r * 2];
            float q1 = S[OFF_DTSR + r * 2 + 1];
            float v0 = fmaf(q0, S[OFF_WDT + d0],      fmaf(q1, S[OFF_WDT + 64 + d0], S[OFF_BDT2 + d0]));
            float v1 = fmaf(q0, S[OFF_WDT + d0 + 32], fmaf(q1, S[OFF_WDT + 96 + d0], S[OFF_BDT2 + d0 + 32]));
            du0[t] = softplusf(v0) * S[OFF_XP + r * 66 + d0];
            du1[t] = softplusf(v1) * S[OFF_XP + r * 66 + d0 + 32];
        }
        ULL hp0[8], hp1[8];
        #pragma unroll
        for (int j = 0; j < 8; j++) { hp0[j] = 0ULL; hp1[j] = 0ULL; }

        if (fast) {
            // forward
            #pragma unroll
            for (int t = 0; t < 8; t++) {
                int r = p * 8 + t;
                float q0 = S[OFF_DTSR + r * 2];
                float q1 = S[OFF_DTSR + r * 2 + 1];
                float v0 = fmaf(q0, S[OFF_WDT + d0],      fmaf(q1, S[OFF_WDT + 64 + d0], S[OFF_BDT2 + d0]));
                float v1 = fmaf(q0, S[OFF_WDT + d0 + 32], fmaf(q1, S[OFF_WDT + 96 + d0], S[OFF_BDT2 + d0 + 32]));
                float r0 = ex2f(-softplusf(v0) * LOG2E);
                float r1 = ex2f(-softplusf(v1) * LOG2E);
                ULL rq0 = dup2(r0 * r0), rq1 = dup2(r1 * r1);
                ULL a0 = pack2(r0, r0 * r0), a1 = pack2(r1, r1 * r1);
                ULL dp0 = dup2(du0[t]), dp1 = dup2(du1[t]);
                ULL y0 = 0ULL, y1 = 0ULL;
                const ULL* Bp = reinterpret_cast<const ULL*>(&S[OFF_B + r * 16]);
                const ULL* Cp = reinterpret_cast<const ULL*>(&S[OFF_C + r * 16]);
                #pragma unroll
                for (int j = 0; j < 8; j++) {
                    ULL Bj = Bp[j], Cj = Cp[j];
                    hp0[j] = f2fma(a0, hp0[j], f2mul(dp0, Bj));
                    hp1[j] = f2fma(a1, hp1[j], f2mul(dp1, Bj));
                    y0 = f2fma(hp0[j], Cj, y0);
                    y1 = f2fma(hp1[j], Cj, y1);
                    if (j < 7) { a0 = f2mul(a0, rq0); a1 = f2mul(a1, rq1); }
                }
                float ya, yb, yc, yd;
                unpack2(y0, ya, yb); unpack2(y1, yc, yd);
                float u0 = S[OFF_XP + r * 66 + d0];
                float u1 = S[OFF_XP + r * 66 + d0 + 32];
                S[OFF_YS + r * 66 + d0]      = fmaf(u0, S[OFF_DS2 + d0], ya + yb);
                S[OFF_YS + r * 66 + d0 + 32] = fmaf(u1, S[OFF_DS2 + d0 + 32], yc + yd);
            }
            // backward + gate
            #pragma unroll
            for (int j = 0; j < 8; j++) { hp0[j] = 0ULL; hp1[j] = 0ULL; }
            #pragma unroll
            for (int t = 7; t >= 0; t--) {
                int r = p * 8 + t;
                float q0 = S[OFF_DTSR + r * 2];
                float q1 = S[OFF_DTSR + r * 2 + 1];
                float v0 = fmaf(q0, S[OFF_WDT + d0],      fmaf(q1, S[OFF_WDT + 64 + d0], S[OFF_BDT2 + d0]));
                float v1 = fmaf(q0, S[OFF_WDT + d0 + 32], fmaf(q1, S[OFF_WDT + 96 + d0], S[OFF_BDT2 + d0 + 32]));
                float r0 = ex2f(-softplusf(v0) * LOG2E);
                float r1 = ex2f(-softplusf(v1) * LOG2E);
                ULL rq0 = dup2(r0 * r0), rq1 = dup2(r1 * r1);
                ULL a0 = pack2(r0, r0 * r0), a1 = pack2(r1, r1 * r1);
                ULL dp0 = dup2(du0[t]), dp1 = dup2(du1[t]);
                ULL y0 = 0ULL, y1 = 0ULL;
                const ULL* Bp = reinterpret_cast<const ULL*>(&S[OFF_B + r * 16]);
                const ULL* Cp = reinterpret_cast<const ULL*>(&S[OFF_C + r * 16]);
                #pragma unroll
                for (int j = 0; j < 8; j++) {
                    ULL Bj = Bp[j], Cj = Cp[j];
                    hp0[j] = f2fma(a0, hp0[j], f2mul(dp0, Bj));
                    hp1[j] = f2fma(a1, hp1[j], f2mul(dp1, Bj));
                    y0 = f2fma(hp0[j], Cj, y0);
                    y1 = f2fma(hp1[j], Cj, y1);
                    if (j < 7) { a0 = f2mul(a0, rq0); a1 = f2mul(a1, rq1); }
                }
                float ya, yb, yc, yd;
                unpack2(y0, ya, yb); unpack2(y1, yc, yd);
                S[OFF_YS + r * 66 + d0]      = (S[OFF_YS + r * 66 + d0]      + ya + yb) * S[OFF_GZ + r * 66 + d0];
                S[OFF_YS + r * 66 + d0 + 32] = (S[OFF_YS + r * 66 + d0 + 32] + yc + yd) * S[OFF_GZ + r * 66 + d0 + 32];
            }
        } else {
            // slow fallback: scalar, A from gmem
            float h0[16], h1[16];
            #pragma unroll
            for (int n = 0; n < 16; n++) { h0[n] = 0.0f; h1[n] = 0.0f; }
            for (int t = 0; t < 8; t++) {
                int r = p * 8 + t;
                float q0 = S[OFF_DTSR + r * 2], q1 = S[OFF_DTSR + r * 2 + 1];
                float dl0 = softplusf(fmaf(q0, S[OFF_WDT + d0],      fmaf(q1, S[OFF_WDT + 64 + d0], S[OFF_BDT2 + d0])));
                float dl1 = softplusf(fmaf(q0, S[OFF_WDT + d0 + 32], fmaf(q1, S[OFF_WDT + 96 + d0], S[OFF_BDT2 + d0 + 32])));
                float y0 = 0.0f, y1 = 0.0f;
                for (int n = 0; n < 16; n++) {
                    float Bn = S[OFF_B + r * 16 + n], Cn = S[OFF_C + r * 16 + n];
                    float a0 = __expf(-dl0 * __expf(__ldg(&A_logs[d0 * 16 + n])));
                    float a1 = __expf(-dl1 * __expf(__ldg(&A_logs[(d0 + 32) * 16 + n])));
                    h0[n] = fmaf(a0, h0[n], du0[t] * Bn);
                    h1[n] = fmaf(a1, h1[n], du1[t] * Bn);
                    y0 = fmaf(h0[n], Cn, y0);
                    y1 = fmaf(h1[n], Cn, y1);
                }
                float u0 = S[OFF_XP + r * 66 + d0], u1 = S[OFF_XP + r * 66 + d0 + 32];
                S[OFF_YS + r * 66 + d0]      = fmaf(u0, S[OFF_DS2 + d0], y0);
                S[OFF_YS + r * 66 + d0 + 32] = fmaf(u1, S[OFF_DS2 + d0 + 32], y1);
            }
            #pragma unroll
            for (int n = 0; n < 16; n++) { h0[n] = 0.0f; h1[n] = 0.0f; }
            for (int t = 7; t >= 0; t--) {
                int r = p * 8 + t;
                float q0 = S[OFF_DTSR + r * 2], q1 = S[OFF_DTSR + r * 2 + 1];
                float dl0 = softplusf(fmaf(q0, S[OFF_WDT + d0],      fmaf(q1, S[OFF_WDT + 64 + d0], S[OFF_BDT2 + d0])));
                float dl1 = softplusf(fmaf(q0, S[OFF_WDT + d0 + 32], fmaf(q1, S[OFF_WDT + 96 + d0], S[OFF_BDT2 + d0 + 32])));
                float y0 = 0.0f, y1 = 0.0f;
                for (int n = 0; n < 16; n++) {
                    float Bn = S[OFF_B + r * 16 + n], Cn = S[OFF_C + r * 16 + n];
                    float a0 = __expf(-dl0 * __expf(__ldg(&A_logs[d0 * 16 + n])));
                    float a1 = __expf(-dl1 * __expf(__ldg(&A_logs[(d0 + 32) * 16 + n])));
                    h0[n] = fmaf(a0, h0[n], du0[t] * Bn);
                    h1[n] = fmaf(a1, h1[n], du1[t] * Bn);
                    y0 = fmaf(h0[n], Cn, y0);
                    y1 = fmaf(h1[n], Cn, y1);
                }
                S[OFF_YS + r * 66 + d0]      = (S[OFF_YS + r * 66 + d0]      + y0) * S[OFF_GZ + r * 66 + d0];
                S[OFF_YS + r * 66 + d0 + 32] = (S[OFF_YS + r * 66 + d0 + 32] + y1) * S[OFF_GZ + r * 66 + d0 + 32];
            }
        }
    }
    __syncthreads();

    // ---------------- GEMM3: [64x64]@[64x32] -> y_pre + group partials ----------------
    {
        const int rp = tid >> 3, cq = tid & 7;
        const int row0 = 2 * rp, row1 = row0 + 1;
        ULL acc0[2], acc1[2];
        acc0[0] = acc0[1] = acc1[0] = acc1[1] = 0ULL;
        #pragma unroll 4
        for (int k = 0; k < 64; k++) {
            const ULL* wp = reinterpret_cast<const ULL*>(&S[OFF_WOUT + k * 32 + 4 * cq]);
            ULL w0 = wp[0], w1 = wp[1];
            ULL a0 = dup2(S[OFF_YS + row0 * 66 + k]);
            ULL a1 = dup2(S[OFF_YS + row1 * 66 + k]);
            acc0[0] = f2fma(a0, w0, acc0[0]);
            acc0[1] = f2fma(a0, w1, acc0[1]);
            acc1[0] = f2fma(a1, w0, acc1[0]);
            acc1[1] = f2fma(a1, w1, acc1[1]);
        }
        int m0 = bid * 8;
        float s = 0.0f, ss = 0.0f;
        {
            int p = row0 >> 3, t = row0 & 7;
            ULL* dst = reinterpret_cast<ULL*>(&g_ypre[(m0 + p) * 256 + t * 32 + 4 * cq]);
            dst[0] = acc0[0]; dst[1] = acc0[1];
            float a, b, c, d;
            unpack2(acc0[0], a, b); unpack2(acc0[1], c, d);
            s += a + b + c + d; ss += a * a + b * b + c * c + d * d;
        }
        {
            int p = row1 >> 3, t = row1 & 7;
            ULL* dst = reinterpret_cast<ULL*>(&g_ypre[(m0 + p) * 256 + t * 32 + 4 * cq]);
            dst[0] = acc1[0]; dst[1] = acc1[1];
            float a, b, c, d;
            unpack2(acc1[0], a, b); unpack2(acc1[1], c, d);
            s += a + b + c + d; ss += a * a + b * b + c * c + d * d;
        }
        #pragma unroll
        for (int off = 4; off; off >>= 1) {
            s  += __shfl_down_sync(0xffffffffu, s,  off, 8);
            ss += __shfl_down_sync(0xffffffffu, ss, off, 8);
        }
        if ((tid & 7) == 0) {
            int w = tid >> 5, g = rp & 3;
            S[OFF_GACC + (w * 4 + g) * 2]     = s;
            S[OFF_GACC + (w * 4 + g) * 2 + 1] = ss;
        }
    }
    __syncthreads();
    if (tid < 8) {
        int g = tid & 3, hh = tid >> 2;
        float v = 0.0f;
        #pragma unroll
        for (int w = 0; w < 8; w++) v += S[OFF_GACC + (w * 4 + g) * 2 + hh];
        g_part[bid * 8 + g * 2 + hh] = v;
    }
}

// ---------------- kernel 2: partials -> 16 stats ----------------
__global__ void k2_stats() {
    __shared__ float ssum[256], ssq[256];
    int b = blockIdx.x >> 2, g = blockIdx.x & 3;
    int tid = threadIdx.x;
    float s = 0.0f, q = 0.0f;
    for (int j = tid; j < 512; j += 256) {
        int blk = b * 512 + j;
        s += g_part[blk * 8 + g * 2];
        q += g_part[blk * 8 + g * 2 + 1];
    }
    ssum[tid] = s; ssq[tid] = q;
    __syncthreads();
    for (int st = 128; st; st >>= 1) {
        if (tid < st) { ssum[tid] += ssum[tid + st]; ssq[tid] += ssq[tid + st]; }
        __syncthreads();
    }
    if (tid == 0) {
        float invN = 1.0f / 262144.0f;
        float mean = ssum[0] * invN;
        float var  = ssq[0] * invN - mean * mean;
        g_stats[blockIdx.x * 2]     = mean;
        g_stats[blockIdx.x * 2 + 1] = rsqrtf(var + 1e-5f);
    }
}

// ---------------- kernel 3: groupnorm affine + transpose + residual ----------------
__global__ __launch_bounds__(256) void k3_final(
    const float* __restrict__ x, const float* __restrict__ gn_w,
    const float* __restrict__ gn_b, float* __restrict__ out)
{
    __shared__ float sm[32][33];
    int tx = threadIdx.x, ty = threadIdx.y;
    int ct = blockIdx.x & 7, wt = blockIdx.x >> 3;
    int h = blockIdx.y, b = blockIdx.z;
    int c0 = ct * 32, w0 = wt * 32;
    int c = c0 + tx;
    int grp = c >> 6;
    float mean = g_stats[(b * 4 + grp) * 2];
    float rsig = g_stats[(b * 4 + grp) * 2 + 1];
    float gw = gn_w[c], gb = gn_b[c];
    const float* yp = g_ypre + ((b * 64 + h) * 64 + w0) * 256;
    #pragma unroll
    for (int i = 0; i < 4; i++) {
        int wl = ty + 8 * i;
        float v = yp[wl * 256 + c];
        sm[wl][tx] = fmaf((v - mean) * rsig, gw, gb);
    }
    __syncthreads();
    #pragma unroll
    for (int i = 0; i < 4; i++) {
        int cl = ty + 8 * i;
        int gi = ((b * 256 + c0 + cl) * 64 + h) * 64 + w0 + tx;
        out[gi] = x[gi] + sm[tx][cl];
    }
}

extern "C" void kernel_launch(void* const* d_in, const int* in_sizes, int n_in,
                              void* d_out, int out_size) {
    const float* x      = (const float*)d_in[0];
    const float* W_in   = (const float*)d_in[1];
    const float* W_x    = (const float*)d_in[2];
    const float* W_dt   = (const float*)d_in[3];
    const float* b_dt   = (const float*)d_in[4];
    const float* A_logs = (const float*)d_in[5];
    const float* Ds     = (const float*)d_in[6];
    const float* W_out  = (const float*)d_in[7];
    const float* gn_w   = (const float*)d_in[8];
    const float* gn_b   = (const float*)d_in[9];
    float* out = (float*)d_out;

    cudaFuncSetAttribute(k1_main, cudaFuncAttributeMaxDynamicSharedMemorySize,
                         SMEM_FLOATS * 4);
    k1_main<<<NBLK1, 256, SMEM_FLOATS * 4>>>(x, W_in, W_x, W_dt, b_dt, A_logs, Ds, W_out);
    k2_stats<<<16, 256>>>();
    k3_final<<<dim3(16, 64, 4), dim3(32, 8)>>>(x, gn_w, gn_b, out);
}

// round 6
// speedup vs baseline: 1.1521x; 1.1521x over previous
#include <cuda_runtime.h>
#include <math.h>

#define NBLK1 2048
#define LOG2E 1.44269504088896f
typedef unsigned long long ULL;

__device__ __align__(16) float g_ypre[4194304];   // (b,h,w,c)
__device__ float g_part[NBLK1 * 8];
__device__ float g_stats[32];

// shared-memory float offsets (packed accesses all 8B-aligned)
#define OFF_WIN   0        // [32][128]
#define OFF_WX    4096     // [64][34]
#define OFF_WOUT  6272     // [64][32]
#define OFF_WDT   8320     // [2][64]
#define OFF_BDT2  8448     // [64]
#define OFF_DS2   8512     // [64]
// union: XF (GEMM1 input) aliases B/C/DTSR (written by GEMM2 after XF dead);
// GACC aliases B (dead after scan).
#define OFF_XF    8576     // [64][33] = 2112
#define OFF_B     8576     // [64][16]
#define OFF_GACC  8576     // [8][4][2] (used only after scan)
#define OFF_C     9600     // [64][16]
#define OFF_DTSR  10624    // [64][2]
#define OFF_XP    10752    // [64][66]  (aliased by YS)
#define OFF_YS    10752
#define OFF_GZ    14976    // [64][64]
#define SMEM_FLOATS 19072  // 76288 B -> 3 CTAs/SM

__device__ __forceinline__ float ex2f(float x) {
    float y; asm("ex2.approx.ftz.f32 %0, %1;" : "=f"(y) : "f"(x)); return y;
}
__device__ __forceinline__ ULL pack2(float lo, float hi) {
    ULL d; asm("mov.b64 %0, {%1, %2};" : "=l"(d) : "f"(lo), "f"(hi)); return d;
}
__device__ __forceinline__ ULL dup2(float v) { return pack2(v, v); }
__device__ __forceinline__ void unpack2(ULL v, float& lo, float& hi) {
    asm("mov.b64 {%0, %1}, %2;" : "=f"(lo), "=f"(hi) : "l"(v));
}
__device__ __forceinline__ ULL f2fma(ULL a, ULL b, ULL c) {
    ULL d; asm("fma.rn.f32x2 %0, %1, %2, %3;" : "=l"(d) : "l"(a), "l"(b), "l"(c)); return d;
}
__device__ __forceinline__ ULL f2mul(ULL a, ULL b) {
    ULL d; asm("mul.rn.f32x2 %0, %1, %2;" : "=l"(d) : "l"(a), "l"(b)); return d;
}
__device__ __forceinline__ float softplusf(float v) {
    float e = __expf(v);
    return (v < -3.0f) ? e * (1.0f - e * (0.5f - 0.33333334f * e)) : log1pf(e);
}
__device__ __forceinline__ float geluf(float v) {
    return 0.5f * v * (1.0f + erff(v * 0.70710678118f));
}

__global__ __launch_bounds__(256, 3) void k1_main(
    const float* __restrict__ x, const float* __restrict__ W_in,
    const float* __restrict__ W_x, const float* __restrict__ W_dt,
    const float* __restrict__ b_dt, const float* __restrict__ A_logs,
    const float* __restrict__ Ds, const float* __restrict__ W_out)
{
    extern __shared__ float S[];
    const int tid = threadIdx.x;
    const int bid = blockIdx.x;

    // ---------------- weights to smem ----------------
    for (int i = tid; i < 4096; i += 256) S[OFF_WIN + i] = W_in[i];
    for (int i = tid; i < 64 * 34; i += 256) S[OFF_WX + i] = W_x[i];
    for (int i = tid; i < 2048; i += 256) S[OFF_WOUT + i] = W_out[i];
    if (tid < 128) S[OFF_WDT + tid] = W_dt[tid];
    if (tid < 64) {
        S[OFF_BDT2 + tid] = 2.0f * b_dt[tid];
        S[OFF_DS2 + tid]  = 2.0f * Ds[tid];
    }
    int ok = 1;
    for (int i = tid; i < 1024; i += 256) {
        int n = i & 15;
        float ae = __expf(A_logs[i]);
        if (fabsf(ae - (float)(n + 1)) > 1e-3f * (float)(n + 1)) ok = 0;
    }

    // ---------------- x tile (8 consecutive w positions) ----------------
    {
        int m0 = bid * 8;
        int b = m0 >> 12;
        int h = (m0 >> 6) & 63;
        int w0 = m0 & 63;
        const float* xb = x + b * (256 * 4096) + h * 64 + w0;
        for (int i = tid; i < 2048; i += 256) {
            int c = i >> 3, p = i & 7;
            int t = c >> 5, g = c & 31;
            S[OFF_XF + (p * 8 + t) * 33 + g] = xb[c * 4096 + p];
        }
    }
    const int fast = __syncthreads_and(ok);

    // ---------------- GEMM1: [64x32]@[32x128] -> xp | gelu(z), packed ----------------
    {
        const int rp = tid >> 3, cg = tid & 7;
        const int row0 = 2 * rp, row1 = row0 + 1;
        ULL acc0[8], acc1[8];
        #pragma unroll
        for (int q = 0; q < 8; q++) { acc0[q] = 0ULL; acc1[q] = 0ULL; }
        const ULL* W4 = reinterpret_cast<const ULL*>(&S[OFF_WIN]);
        #pragma unroll 4
        for (int k = 0; k < 32; k++) {
            ULL a0p = dup2(S[OFF_XF + row0 * 33 + k]);
            ULL a1p = dup2(S[OFF_XF + row1 * 33 + k]);
            const ULL* wrow = W4 + k * 64 + cg * 8;
            #pragma unroll
            for (int q = 0; q < 8; q++) {
                ULL w = wrow[q];
                acc0[q] = f2fma(a0p, w, acc0[q]);
                acc1[q] = f2fma(a1p, w, acc1[q]);
            }
        }
        if (cg < 4) {
            ULL* X0 = reinterpret_cast<ULL*>(&S[OFF_XP + row0 * 66 + cg * 16]);
            ULL* X1 = reinterpret_cast<ULL*>(&S[OFF_XP + row1 * 66 + cg * 16]);
            #pragma unroll
            for (int q = 0; q < 8; q++) { X0[q] = acc0[q]; X1[q] = acc1[q]; }
        } else {
            int c0 = (cg - 4) * 16;
            #pragma unroll
            for (int q = 0; q < 8; q++) {
                float v0, v1, w0, w1;
                unpack2(acc0[q], v0, v1);
                unpack2(acc1[q], w0, w1);
                S[OFF_GZ + row0 * 64 + c0 + 2 * q]     = geluf(v0);
                S[OFF_GZ + row0 * 64 + c0 + 2 * q + 1] = geluf(v1);
                S[OFF_GZ + row1 * 64 + c0 + 2 * q]     = geluf(w0);
                S[OFF_GZ + row1 * 64 + c0 + 2 * q + 1] = geluf(w1);
            }
        }
    }
    __syncthreads();

    // ---------------- GEMM2: [64x64]@[64x34] -> dts(0,1)|B(2..17)|C(18..33) ----------------
    if (tid < 128) {
        const int rq = tid >> 3, cq = tid & 7;
        ULL accp[4][2];
        #pragma unroll
        for (int i = 0; i < 4; i++) { accp[i][0] = 0ULL; accp[i][1] = 0ULL; }
        #pragma unroll 4
        for (int k = 0; k < 64; k++) {
            const ULL* wp = reinterpret_cast<const ULL*>(&S[OFF_WX + k * 34 + 4 * cq]);
            ULL w0 = wp[0], w1 = wp[1];
            #pragma unroll
            for (int i = 0; i < 4; i++) {
                ULL ap = dup2(S[OFF_XP + (4 * rq + i) * 66 + k]);
                accp[i][0] = f2fma(ap, w0, accp[i][0]);
                accp[i][1] = f2fma(ap, w1, accp[i][1]);
            }
        }
        #pragma unroll
        for (int i = 0; i < 4; i++) {
            int r = 4 * rq + i;
            #pragma unroll
            for (int pp = 0; pp < 2; pp++) {
                int c0 = 4 * cq + 2 * pp;
                ULL v = accp[i][pp];
                if (c0 == 0)
                    reinterpret_cast<ULL*>(&S[OFF_DTSR])[r] = v;
                else if (c0 < 18)
                    *reinterpret_cast<ULL*>(&S[OFF_B + r * 16 + (c0 - 2)]) = v;
                else
                    *reinterpret_cast<ULL*>(&S[OFF_C + r * 16 + (c0 - 18)]) = v;
            }
        }
    } else if (tid < 192) {
        // cols 32,33 -> C[14],C[15]
        int r = tid - 128;
        ULL acc = 0ULL;
        #pragma unroll 8
        for (int k = 0; k < 64; k++) {
            ULL w = *reinterpret_cast<const ULL*>(&S[OFF_WX + k * 34 + 32]);
            acc = f2fma(dup2(S[OFF_XP + r * 66 + k]), w, acc);
        }
        *reinterpret_cast<ULL*>(&S[OFF_C + r * 16 + 14]) = acc;
    }
    __syncthreads();

    // ---------------- bidirectional selective scan (packed, no spill arrays) ----------
    {
        const int p  = tid >> 5;
        const int d0 = tid & 31;
        ULL hp0[8], hp1[8];
        #pragma unroll
        for (int j = 0; j < 8; j++) { hp0[j] = 0ULL; hp1[j] = 0ULL; }

        if (fast) {
            // forward
            #pragma unroll
            for (int t = 0; t < 8; t++) {
                int r = p * 8 + t;
                float q0 = S[OFF_DTSR + r * 2];
                float q1 = S[OFF_DTSR + r * 2 + 1];
                float v0 = fmaf(q0, S[OFF_WDT + d0],      fmaf(q1, S[OFF_WDT + 64 + d0], S[OFF_BDT2 + d0]));
                float v1 = fmaf(q0, S[OFF_WDT + d0 + 32], fmaf(q1, S[OFF_WDT + 96 + d0], S[OFF_BDT2 + d0 + 32]));
                float sp0 = softplusf(v0), sp1 = softplusf(v1);
                float u0 = S[OFF_XP + r * 66 + d0];
                float u1 = S[OFF_XP + r * 66 + d0 + 32];
                float r0 = ex2f(-sp0 * LOG2E);
                float r1 = ex2f(-sp1 * LOG2E);
                ULL rq0 = dup2(r0 * r0), rq1 = dup2(r1 * r1);
                ULL a0 = pack2(r0, r0 * r0), a1 = pack2(r1, r1 * r1);
                ULL dp0 = dup2(sp0 * u0), dp1 = dup2(sp1 * u1);
                ULL y0 = 0ULL, y1 = 0ULL;
                const ULL* Bp = reinterpret_cast<const ULL*>(&S[OFF_B + r * 16]);
                const ULL* Cp = reinterpret_cast<const ULL*>(&S[OFF_C + r * 16]);
                #pragma unroll
                for (int j = 0; j < 8; j++) {
                    ULL Bj = Bp[j], Cj = Cp[j];
                    hp0[j] = f2fma(a0, hp0[j], f2mul(dp0, Bj));
                    hp1[j] = f2fma(a1, hp1[j], f2mul(dp1, Bj));
                    y0 = f2fma(hp0[j], Cj, y0);
                    y1 = f2fma(hp1[j], Cj, y1);
                    if (j < 7) { a0 = f2mul(a0, rq0); a1 = f2mul(a1, rq1); }
                }
                float ya, yb, yc, yd;
                unpack2(y0, ya, yb); unpack2(y1, yc, yd);
                S[OFF_YS + r * 66 + d0]      = fmaf(u0, S[OFF_DS2 + d0], ya + yb);
                S[OFF_YS + r * 66 + d0 + 32] = fmaf(u1, S[OFF_DS2 + d0 + 32], yc + yd);
            }
            // backward + gate
            #pragma unroll
            for (int j = 0; j < 8; j++) { hp0[j] = 0ULL; hp1[j] = 0ULL; }
            #pragma unroll
            for (int t = 7; t >= 0; t--) {
                int r = p * 8 + t;
                float q0 = S[OFF_DTSR + r * 2];
                float q1 = S[OFF_DTSR + r * 2 + 1];
                float v0 = fmaf(q0, S[OFF_WDT + d0],      fmaf(q1, S[OFF_WDT + 64 + d0], S[OFF_BDT2 + d0]));
                float v1 = fmaf(q0, S[OFF_WDT + d0 + 32], fmaf(q1, S[OFF_WDT + 96 + d0], S[OFF_BDT2 + d0 + 32]));
                float sp0 = softplusf(v0), sp1 = softplusf(v1);
                float u0 = S[OFF_XP + r * 66 + d0];
                float u1 = S[OFF_XP + r * 66 + d0 + 32];
                float r0 = ex2f(-sp0 * LOG2E);
                float r1 = ex2f(-sp1 * LOG2E);
                ULL rq0 = dup2(r0 * r0), rq1 = dup2(r1 * r1);
                ULL a0 = pack2(r0, r0 * r0), a1 = pack2(r1, r1 * r1);
                ULL dp0 = dup2(sp0 * u0), dp1 = dup2(sp1 * u1);
                ULL y0 = 0ULL, y1 = 0ULL;
                const ULL* Bp = reinterpret_cast<const ULL*>(&S[OFF_B + r * 16]);
                const ULL* Cp = reinterpret_cast<const ULL*>(&S[OFF_C + r * 16]);
                #pragma unroll
                for (int j = 0; j < 8; j++) {
                    ULL Bj = Bp[j], Cj = Cp[j];
                    hp0[j] = f2fma(a0, hp0[j], f2mul(dp0, Bj));
                    hp1[j] = f2fma(a1, hp1[j], f2mul(dp1, Bj));
                    y0 = f2fma(hp0[j], Cj, y0);
                    y1 = f2fma(hp1[j], Cj, y1);
                    if (j < 7) { a0 = f2mul(a0, rq0); a1 = f2mul(a1, rq1); }
                }
                float ya, yb, yc, yd;
                unpack2(y0, ya, yb); unpack2(y1, yc, yd);
                S[OFF_YS + r * 66 + d0]      = (S[OFF_YS + r * 66 + d0]      + ya + yb) * S[OFF_GZ + r * 64 + d0];
                S[OFF_YS + r * 66 + d0 + 32] = (S[OFF_YS + r * 66 + d0 + 32] + yc + yd) * S[OFF_GZ + r * 64 + d0 + 32];
            }
        } else {
            // slow fallback: same register pool, decays from gmem A_logs
            #pragma unroll 1
            for (int t = 0; t < 8; t++) {
                int r = p * 8 + t;
                float q0 = S[OFF_DTSR + r * 2], q1 = S[OFF_DTSR + r * 2 + 1];
                float sp0 = softplusf(fmaf(q0, S[OFF_WDT + d0],      fmaf(q1, S[OFF_WDT + 64 + d0], S[OFF_BDT2 + d0])));
                float sp1 = softplusf(fmaf(q0, S[OFF_WDT + d0 + 32], fmaf(q1, S[OFF_WDT + 96 + d0], S[OFF_BDT2 + d0 + 32])));
                float u0 = S[OFF_XP + r * 66 + d0];
                float u1 = S[OFF_XP + r * 66 + d0 + 32];
                ULL dp0 = dup2(sp0 * u0), dp1 = dup2(sp1 * u1);
                ULL y0 = 0ULL, y1 = 0ULL;
                const ULL* Bp = reinterpret_cast<const ULL*>(&S[OFF_B + r * 16]);
                const ULL* Cp = reinterpret_cast<const ULL*>(&S[OFF_C + r * 16]);
                #pragma unroll 1
                for (int j = 0; j < 8; j++) {
                    ULL a0 = pack2(__expf(-sp0 * __expf(__ldg(&A_logs[d0 * 16 + 2 * j]))),
                                   __expf(-sp0 * __expf(__ldg(&A_logs[d0 * 16 + 2 * j + 1]))));
                    ULL a1 = pack2(__expf(-sp1 * __expf(__ldg(&A_logs[(d0 + 32) * 16 + 2 * j]))),
                                   __expf(-sp1 * __expf(__ldg(&A_logs[(d0 + 32) * 16 + 2 * j + 1]))));
                    hp0[j] = f2fma(a0, hp0[j], f2mul(dp0, Bp[j]));
                    hp1[j] = f2fma(a1, hp1[j], f2mul(dp1, Bp[j]));
                    y0 = f2fma(hp0[j], Cp[j], y0);
                    y1 = f2fma(hp1[j], Cp[j], y1);
                }
                float ya, yb, yc, yd;
                unpack2(y0, ya, yb); unpack2(y1, yc, yd);
                S[OFF_YS + r * 66 + d0]      = fmaf(u0, S[OFF_DS2 + d0], ya + yb);
                S[OFF_YS + r * 66 + d0 + 32] = fmaf(u1, S[OFF_DS2 + d0 + 32], yc + yd);
            }
            #pragma unroll
            for (int j = 0; j < 8; j++) { hp0[j] = 0ULL; hp1[j] = 0ULL; }
            #pragma unroll 1
            for (int t = 7; t >= 0; t--) {
                int r = p * 8 + t;
                float q0 = S[OFF_DTSR + r * 2], q1 = S[OFF_DTSR + r * 2 + 1];
                float sp0 = softplusf(fmaf(q0, S[OFF_WDT + d0],      fmaf(q1, S[OFF_WDT + 64 + d0], S[OFF_BDT2 + d0])));
                float sp1 = softplusf(fmaf(q0, S[OFF_WDT + d0 + 32], fmaf(q1, S[OFF_WDT + 96 + d0], S[OFF_BDT2 + d0 + 32])));
                float u0 = S[OFF_XP + r * 66 + d0];
                float u1 = S[OFF_XP + r * 66 + d0 + 32];
                ULL dp0 = dup2(sp0 * u0), dp1 = dup2(sp1 * u1);
                ULL y0 = 0ULL, y1 = 0ULL;
                const ULL* Bp = reinterpret_cast<const ULL*>(&S[OFF_B + r * 16]);
                const ULL* Cp = reinterpret_cast<const ULL*>(&S[OFF_C + r * 16]);
                #pragma unroll 1
                for (int j = 0; j < 8; j++) {
                    ULL a0 = pack2(__expf(-sp0 * __expf(__ldg(&A_logs[d0 * 16 + 2 * j]))),
                                   __expf(-sp0 * __expf(__ldg(&A_logs[d0 * 16 + 2 * j + 1]))));
                    ULL a1 = pack2(__expf(-sp1 * __expf(__ldg(&A_logs[(d0 + 32) * 16 + 2 * j]))),
                                   __expf(-sp1 * __expf(__ldg(&A_logs[(d0 + 32) * 16 + 2 * j + 1]))));
                    hp0[j] = f2fma(a0, hp0[j], f2mul(dp0, Bp[j]));
                    hp1[j] = f2fma(a1, hp1[j], f2mul(dp1, Bp[j]));
                    y0 = f2fma(hp0[j], Cp[j], y0);
                    y1 = f2fma(hp1[j], Cp[j], y1);
                }
                float ya, yb, yc, yd;
                unpack2(y0, ya, yb); unpack2(y1, yc, yd);
                S[OFF_YS + r * 66 + d0]      = (S[OFF_YS + r * 66 + d0]      + ya + yb) * S[OFF_GZ + r * 64 + d0];
                S[OFF_YS + r * 66 + d0 + 32] = (S[OFF_YS + r * 66 + d0 + 32] + yc + yd) * S[OFF_GZ + r * 64 + d0 + 32];
            }
        }
    }
    __syncthreads();

    // ---------------- GEMM3: [64x64]@[64x32] -> y_pre + group partials ----------------
    {
        const int rp = tid >> 3, cq = tid & 7;
        const int row0 = 2 * rp, row1 = row0 + 1;
        ULL acc0[2], acc1[2];
        acc0[0] = acc0[1] = acc1[0] = acc1[1] = 0ULL;
        #pragma unroll 4
        for (int k = 0; k < 64; k++) {
            const ULL* wp = reinterpret_cast<const ULL*>(&S[OFF_WOUT + k * 32 + 4 * cq]);
            ULL w0 = wp[0], w1 = wp[1];
            ULL a0 = dup2(S[OFF_YS + row0 * 66 + k]);
            ULL a1 = dup2(S[OFF_YS + row1 * 66 + k]);
            acc0[0] = f2fma(a0, w0, acc0[0]);
            acc0[1] = f2fma(a0, w1, acc0[1]);
            acc1[0] = f2fma(a1, w0, acc1[0]);
            acc1[1] = f2fma(a1, w1, acc1[1]);
        }
        int m0 = bid * 8;
        float s = 0.0f, ss = 0.0f;
        {
            int p = row0 >> 3, t = row0 & 7;
            ULL* dst = reinterpret_cast<ULL*>(&g_ypre[(m0 + p) * 256 + t * 32 + 4 * cq]);
            dst[0] = acc0[0]; dst[1] = acc0[1];
            float a, b, c, d;
            unpack2(acc0[0], a, b); unpack2(acc0[1], c, d);
            s += a + b + c + d; ss += a * a + b * b + c * c + d * d;
        }
        {
            int p = row1 >> 3, t = row1 & 7;
            ULL* dst = reinterpret_cast<ULL*>(&g_ypre[(m0 + p) * 256 + t * 32 + 4 * cq]);
            dst[0] = acc1[0]; dst[1] = acc1[1];
            float a, b, c, d;
            unpack2(acc1[0], a, b); unpack2(acc1[1], c, d);
            s += a + b + c + d; ss += a * a + b * b + c * c + d * d;
        }
        #pragma unroll
        for (int off = 4; off; off >>= 1) {
            s  += __shfl_down_sync(0xffffffffu, s,  off, 8);
            ss += __shfl_down_sync(0xffffffffu, ss, off, 8);
        }
        __syncthreads();   // B/C region now dead; GACC aliases it
        if ((tid & 7) == 0) {
            int w = tid >> 5, g = rp & 3;
            S[OFF_GACC + (w * 4 + g) * 2]     = s;
            S[OFF_GACC + (w * 4 + g) * 2 + 1] = ss;
        }
    }
    __syncthreads();
    if (tid < 8) {
        int g = tid & 3, hh = tid >> 2;
        float v = 0.0f;
        #pragma unroll
        for (int w = 0; w < 8; w++) v += S[OFF_GACC + (w * 4 + g) * 2 + hh];
        g_part[bid * 8 + g * 2 + hh] = v;
    }
}

// ---------------- kernel 2: partials -> 16 stats ----------------
__global__ void k2_stats() {
    __shared__ float ssum[256], ssq[256];
    int b = blockIdx.x >> 2, g = blockIdx.x & 3;
    int tid = threadIdx.x;
    float s = 0.0f, q = 0.0f;
    for (int j = tid; j < 512; j += 256) {
        int blk = b * 512 + j;
        s += g_part[blk * 8 + g * 2];
        q += g_part[blk * 8 + g * 2 + 1];
    }
    ssum[tid] = s; ssq[tid] = q;
    __syncthreads();
    for (int st = 128; st; st >>= 1) {
        if (tid < st) { ssum[tid] += ssum[tid + st]; ssq[tid] += ssq[tid + st]; }
        __syncthreads();
    }
    if (tid == 0) {
        float invN = 1.0f / 262144.0f;
        float mean = ssum[0] * invN;
        float var  = ssq[0] * invN - mean * mean;
        g_stats[blockIdx.x * 2]     = mean;
        g_stats[blockIdx.x * 2 + 1] = rsqrtf(var + 1e-5f);
    }
}

// ---------------- kernel 3: groupnorm affine + transpose + residual ----------------
__global__ __launch_bounds__(256) void k3_final(
    const float* __restrict__ x, const float* __restrict__ gn_w,
    const float* __restrict__ gn_b, float* __restrict__ out)
{
    __shared__ float sm[32][33];
    int tx = threadIdx.x, ty = threadIdx.y;
    int ct = blockIdx.x & 7, wt = blockIdx.x >> 3;
    int h = blockIdx.y, b = blockIdx.z;
    int c0 = ct * 32, w0 = wt * 32;
    int c = c0 + tx;
    int grp = c >> 6;
    float mean = g_stats[(b * 4 + grp) * 2];
    float rsig = g_stats[(b * 4 + grp) * 2 + 1];
    float gw = gn_w[c], gb = gn_b[c];
    const float* yp = g_ypre + ((b * 64 + h) * 64 + w0) * 256;
    #pragma unroll
    for (int i = 0; i < 4; i++) {
        int wl = ty + 8 * i;
        float v = yp[wl * 256 + c];
        sm[wl][tx] = fmaf((v - mean) * rsig, gw, gb);
    }
    __syncthreads();
    #pragma unroll
    for (int i = 0; i < 4; i++) {
        int cl = ty + 8 * i;
        int gi = ((b * 256 + c0 + cl) * 64 + h) * 64 + w0 + tx;
        out[gi] = x[gi] + sm[tx][cl];
    }
}

extern "C" void kernel_launch(void* const* d_in, const int* in_sizes, int n_in,
                              void* d_out, int out_size) {
    const float* x      = (const float*)d_in[0];
    const float* W_in   = (const float*)d_in[1];
    const float* W_x    = (const float*)d_in[2];
    const float* W_dt   = (const float*)d_in[3];
    const float* b_dt   = (const float*)d_in[4];
    const float* A_logs = (const float*)d_in[5];
    const float* Ds     = (const float*)d_in[6];
    const float* W_out  = (const float*)d_in[7];
    const float* gn_w   = (const float*)d_in[8];
    const float* gn_b   = (const float*)d_in[9];
    float* out = (float*)d_out;

    cudaFuncSetAttribute(k1_main, cudaFuncAttributeMaxDynamicSharedMemorySize,
                         SMEM_FLOATS * 4);
    k1_main<<<NBLK1, 256, SMEM_FLOATS * 4>>>(x, W_in, W_x, W_dt, b_dt, A_logs, Ds, W_out);
    k2_stats<<<16, 256>>>();
    k3_final<<<dim3(16, 64, 4), dim3(32, 8)>>>(x, gn_w, gn_b, out);
}